// round 11
// baseline (speedup 1.0000x reference)
#include <cuda_runtime.h>

#define N_NODES   50000
#define N_REL     10
#define R2        21
#define N_TRIPLES 500000
#define ETOT      (2 * N_TRIPLES + N_NODES)   // 1,050,000 augmented edges
#define BATCH     16384
#define KEYN      (N_NODES * R2)              // keys (src*21+p)
#define SCAN_CHUNK 4096
#define SCAN_NB   ((KEYN + SCAN_CHUNK - 1) / SCAN_CHUNK)   // 257
#define MAXFLAG   32768
#define NPW       4                           // nodes per warp in layer2

// Static scratch (no runtime allocation)
__device__ int   g_colsum[KEYN];
__device__ int   g_keycnt[KEYN];
__device__ int   g_keyoff[KEYN];
__device__ int   g_scanblk[512];
__device__ int   g_sorted[ETOT];
__device__ float g_h[N_NODES * 64];
__device__ float g_nodes[N_NODES * 64];
__device__ int   g_flag[N_NODES];
__device__ int   g_list[N_NODES];
__device__ int   g_cnt[1];
// Interleaved w1 for FFMA2 flush: [p][k2][lane] ulonglong2 where
//  .x = pack(w1[p][2*k2  ][2*lane], w1[p][2*k2  ][2*lane+1])
//  .y = pack(w1[p][2*k2+1][2*lane], w1[p][2*k2+1][2*lane+1])
__device__ ulonglong2 g_w1i[R2 * 32 * 32];

__device__ __forceinline__ unsigned long long pack2(float x, float y) {
    unsigned long long r;
    asm("mov.b64 %0, {%1, %2};" : "=l"(r) : "f"(x), "f"(y));
    return r;
}
__device__ __forceinline__ unsigned long long dup2(float x) {
    unsigned long long r;
    asm("mov.b64 %0, {%1, %1};" : "=l"(r) : "f"(x));
    return r;
}
__device__ __forceinline__ void unpack2(float& x, float& y, unsigned long long v) {
    asm("mov.b64 {%0, %1}, %2;" : "=f"(x), "=f"(y) : "l"(v));
}
__device__ __forceinline__ void ffma2(unsigned long long& acc,
                                      unsigned long long a, unsigned long long b) {
    asm("fma.rn.f32x2 %0, %1, %2, %0;" : "+l"(acc) : "l"(a), "l"(b));
}

__device__ __forceinline__ void decode_edge(int idx, const int* __restrict__ triples,
                                            int& src, int& p, int& o) {
    if (idx < N_TRIPLES) {
        src = triples[3 * idx + 0];
        p   = triples[3 * idx + 1];
        o   = triples[3 * idx + 2];
    } else if (idx < N_TRIPLES + N_NODES) {
        int i = idx - N_TRIPLES;
        src = i; p = 2 * N_REL; o = i;
    } else {
        int e = idx - N_TRIPLES - N_NODES;
        src = triples[3 * e + 2];
        p   = triples[3 * e + 1] + N_REL;
        o   = triples[3 * e + 0];
    }
}

// ---------------------------------------------------------------------------
// K0: zero counters + build interleaved w1 (disjoint arrays, safe to fuse)
// ---------------------------------------------------------------------------
__global__ void k_init(const float* __restrict__ w1) {
    int idx = blockIdx.x * blockDim.x + threadIdx.x;
    if (idx < KEYN) { g_colsum[idx] = 0; g_keycnt[idx] = 0; }
    if (idx < N_NODES) g_flag[idx] = 0;
    if (idx == 0) g_cnt[0] = 0;
    if (idx < R2 * 32 * 32) {
        int p = idx >> 10, rem = idx & 1023;
        int k2 = rem >> 5, lane = rem & 31;
        const float* base = w1 + p * 4096;
        float a0  = __ldg(base + (2 * k2)     * 64 + 2 * lane);
        float a1  = __ldg(base + (2 * k2)     * 64 + 2 * lane + 1);
        float b0  = __ldg(base + (2 * k2 + 1) * 64 + 2 * lane);
        float b1v = __ldg(base + (2 * k2 + 1) * 64 + 2 * lane + 1);
        ulonglong2 v;
        v.x = pack2(a0, a1);
        v.y = pack2(b0, b1v);
        g_w1i[idx] = v;
    }
}

// ---------------------------------------------------------------------------
__global__ void k_hist(const int* __restrict__ triples) {
    int idx = blockIdx.x * blockDim.x + threadIdx.x;
    if (idx >= ETOT) return;
    int src, p, o;
    decode_edge(idx, triples, src, p, o);
    atomicAdd(&g_colsum[p * N_NODES + o], 1);
    atomicAdd(&g_keycnt[src * R2 + p], 1);
}

// ---------------------------------------------------------------------------
// 3-pass exclusive scan of g_keycnt -> g_keyoff
// ---------------------------------------------------------------------------
__global__ void k_scanA() {
    int b = blockIdx.x, tid = threadIdx.x;
    int base = b * SCAN_CHUNK + tid * 16;
    int s = 0;
    #pragma unroll
    for (int j = 0; j < 16; j++) {
        int idx = base + j;
        if (idx < KEYN) s += g_keycnt[idx];
    }
    __shared__ int sh[256];
    sh[tid] = s; __syncthreads();
    for (int off = 128; off; off >>= 1) {
        if (tid < off) sh[tid] += sh[tid + off];
        __syncthreads();
    }
    if (tid == 0) g_scanblk[b] = sh[0];
}

__global__ void k_scanB() {
    int tid = threadIdx.x;              // 512 threads, 1 block
    __shared__ int sh[512];
    int orig = (tid < SCAN_NB) ? g_scanblk[tid] : 0;
    sh[tid] = orig; __syncthreads();
    for (int off = 1; off < 512; off <<= 1) {
        int add = (tid >= off) ? sh[tid - off] : 0;
        __syncthreads();
        sh[tid] += add;
        __syncthreads();
    }
    if (tid < SCAN_NB) g_scanblk[tid] = sh[tid] - orig;   // exclusive
}

__global__ void k_scanC() {
    int b = blockIdx.x, tid = threadIdx.x;
    int base = b * SCAN_CHUNK + tid * 16;
    int v[16];
    #pragma unroll
    for (int j = 0; j < 16; j++) {
        int idx = base + j;
        v[j] = (idx < KEYN) ? g_keycnt[idx] : 0;
    }
    int tot = 0;
    #pragma unroll
    for (int j = 0; j < 16; j++) { int t = v[j]; v[j] = tot; tot += t; }
    __shared__ int sh[256];
    sh[tid] = tot; __syncthreads();
    int orig = tot;
    for (int off = 1; off < 256; off <<= 1) {
        int add = (tid >= off) ? sh[tid - off] : 0;
        __syncthreads();
        sh[tid] += add;
        __syncthreads();
    }
    int texcl = sh[tid] - orig + g_scanblk[b];
    #pragma unroll
    for (int j = 0; j < 16; j++) {
        int idx = base + j;
        if (idx < KEYN) g_keyoff[idx] = texcl + v[j];
    }
}

// ---------------------------------------------------------------------------
// Scatter: after this, g_keyoff[k] = exclusive END of key k
// ---------------------------------------------------------------------------
__global__ void k_scatter(const int* __restrict__ triples) {
    int idx = blockIdx.x * blockDim.x + threadIdx.x;
    if (idx >= ETOT) return;
    int src, p, o;
    decode_edge(idx, triples, src, p, o);
    int pos = atomicAdd(&g_keyoff[src * R2 + p], 1);
    g_sorted[pos] = (p << 16) | o;
}

// ---------------------------------------------------------------------------
// Layer 1: 16-thread group per node, register accumulation, no atomics.
// ---------------------------------------------------------------------------
__global__ void k_layer1(const float* __restrict__ w0, const float* __restrict__ b0) {
    int t = blockIdx.x * blockDim.x + threadIdx.x;
    int u = t >> 4, lane = t & 15;
    if (u >= N_NODES) return;
    int s = (u == 0) ? 0 : g_keyoff[u * R2 - 1];
    int e = g_keyoff[u * R2 + R2 - 1];

    const float4* w0f4 = reinterpret_cast<const float4*>(w0);
    float4 acc = make_float4(0.f, 0.f, 0.f, 0.f);
    for (int i = s; i < e; i++) {
        int packed = g_sorted[i];
        int p = packed >> 16, o = packed & 0xFFFF;
        int col = p * N_NODES + o;
        float val = 1.0f / (float)g_colsum[col];
        float4 w = __ldg(w0f4 + (size_t)col * 16 + lane);
        acc.x = fmaf(val, w.x, acc.x);
        acc.y = fmaf(val, w.y, acc.y);
        acc.z = fmaf(val, w.z, acc.z);
        acc.w = fmaf(val, w.w, acc.w);
    }
    float4 bb = __ldg(reinterpret_cast<const float4*>(b0) + lane);
    float4 r = make_float4(bb.x + acc.x, bb.y + acc.y, bb.z + acc.z, bb.w + acc.w);
    *reinterpret_cast<float4*>(g_h + u * 64 + lane * 4) = r;
}

// ---------------------------------------------------------------------------
__global__ void k_flag(const int* __restrict__ batch) {
    int b = blockIdx.x * blockDim.x + threadIdx.x;
    if (b < BATCH) {
        g_flag[batch[3 * b + 0]] = 1;
        g_flag[batch[3 * b + 2]] = 1;
    }
}

__global__ void k_compact() {
    int u = blockIdx.x * blockDim.x + threadIdx.x;
    if (u < N_NODES && g_flag[u]) {
        int i = atomicAdd(&g_cnt[0], 1);
        g_list[i] = u;
    }
}

// ---------------------------------------------------------------------------
// Layer 2: one warp per NPW=4 flagged nodes. Iterate p = 0..20; per p, read
// each node's (u,p) segment bounds directly from g_keyoff (consecutive keys,
// running "prev" pointer -> 1 LDG per (node,p)), accumulate the 4 hsums,
// stage in shared, then ONE W_p load feeds up to 4 accumulators (empty
// nodes skipped). W L1 traffic amortized 4x vs one-node-per-warp.
// ---------------------------------------------------------------------------
__global__ void k_layer2(const float* __restrict__ b1) {
    int t = blockIdx.x * blockDim.x + threadIdx.x;
    int w = t >> 5, lane = t & 31;
    int wid = threadIdx.x >> 5;
    __shared__ __align__(16) float hs[8][NPW][64];

    int cnt = g_cnt[0];
    int base = w * NPW;
    if (base >= cnt) return;
    int nn = min(NPW, cnt - base);

    int u[NPW], prev[NPW];
    unsigned long long acc[NPW];
    #pragma unroll
    for (int n = 0; n < NPW; n++) {
        int un = (n < nn) ? g_list[base + n] : g_list[base];  // clamp (masked later)
        u[n] = un;
        prev[n] = (un == 0) ? 0 : g_keyoff[un * R2 - 1];
        acc[n] = 0ull;
    }

    for (int p = 0; p < R2; p++) {
        bool need[NPW];
        bool any = false;
        #pragma unroll
        for (int n = 0; n < NPW; n++) {
            int s = prev[n];
            int e = g_keyoff[u[n] * R2 + p];
            prev[n] = e;
            bool active = (n < nn) && (e > s);
            need[n] = active;
            if (active) {
                any = true;
                float2 hacc = make_float2(0.f, 0.f);
                for (int i = s; i < e; i++) {
                    int o = g_sorted[i] & 0xFFFF;
                    float val = 1.0f / (float)g_colsum[p * N_NODES + o];
                    float2 hv = *reinterpret_cast<const float2*>(g_h + o * 64 + 2 * lane);
                    hacc.x = fmaf(val, hv.x, hacc.x);
                    hacc.y = fmaf(val, hv.y, hacc.y);
                }
                *reinterpret_cast<float2*>(&hs[wid][n][2 * lane]) = hacc;
            }
        }
        if (!any) continue;
        __syncwarp();

        const ulonglong2* W = g_w1i + p * 1024 + lane;   // stride 32 per k2
        #pragma unroll 4
        for (int j = 0; j < 16; j++) {
            ulonglong2 w01 = __ldg(W + (2 * j) * 32);       // k = 4j, 4j+1
            ulonglong2 w23 = __ldg(W + (2 * j + 1) * 32);   // k = 4j+2, 4j+3
            #pragma unroll
            for (int n = 0; n < NPW; n++) {
                if (need[n]) {
                    float4 h4 = *reinterpret_cast<const float4*>(&hs[wid][n][4 * j]);
                    ffma2(acc[n], dup2(h4.x), w01.x);
                    ffma2(acc[n], dup2(h4.y), w01.y);
                    ffma2(acc[n], dup2(h4.z), w23.x);
                    ffma2(acc[n], dup2(h4.w), w23.y);
                }
            }
        }
        __syncwarp();
    }

    float2 bb = *reinterpret_cast<const float2*>(b1 + 2 * lane);
    #pragma unroll
    for (int n = 0; n < NPW; n++) {
        if (n < nn) {
            float c0, c1;
            unpack2(c0, c1, acc[n]);
            float2 r = make_float2(bb.x + c0, bb.y + c1);
            *reinterpret_cast<float2*>(g_nodes + u[n] * 64 + 2 * lane) = r;
        }
    }
}

// ---------------------------------------------------------------------------
__global__ void k_score(const int* __restrict__ batch, const float* __restrict__ rel,
                        float* __restrict__ out) {
    int t = blockIdx.x * blockDim.x + threadIdx.x;
    int b = t >> 5, lane = t & 31;
    if (b >= BATCH) return;
    int si = batch[3 * b + 0];
    int pi = batch[3 * b + 1];
    int oi = batch[3 * b + 2];
    const float* ns = g_nodes + si * 64;
    const float* no = g_nodes + oi * 64;
    const float* rr = rel + pi * 64;
    float a = ns[lane]      * rr[lane]      * no[lane]
            + ns[lane + 32] * rr[lane + 32] * no[lane + 32];
    #pragma unroll
    for (int off = 16; off; off >>= 1)
        a += __shfl_xor_sync(0xffffffffu, a, off);
    if (lane == 0) out[b] = a;
}

// ---------------------------------------------------------------------------
extern "C" void kernel_launch(void* const* d_in, const int* in_sizes, int n_in,
                              void* d_out, int out_size) {
    const int*   batch     = (const int*)  d_in[0];
    const int*   triples   = (const int*)  d_in[1];
    const float* w0        = (const float*)d_in[2];
    const float* b0        = (const float*)d_in[3];
    const float* w1        = (const float*)d_in[4];
    const float* b1        = (const float*)d_in[5];
    const float* relations = (const float*)d_in[6];
    float* out = (float*)d_out;

    const int TPB = 256;

    k_init<<<(KEYN + TPB - 1) / TPB, TPB>>>(w1);
    k_hist<<<(ETOT + TPB - 1) / TPB, TPB>>>(triples);
    k_scanA<<<SCAN_NB, 256>>>();
    k_scanB<<<1, 512>>>();
    k_scanC<<<SCAN_NB, 256>>>();
    k_scatter<<<(ETOT + TPB - 1) / TPB, TPB>>>(triples);
    k_layer1<<<(N_NODES * 16 + TPB - 1) / TPB, TPB>>>(w0, b0);
    k_flag<<<(BATCH + TPB - 1) / TPB, TPB>>>(batch);
    k_compact<<<(N_NODES + TPB - 1) / TPB, TPB>>>();
    {
        int warps = (MAXFLAG + NPW - 1) / NPW;           // 8192 warps
        k_layer2<<<(warps * 32 + TPB - 1) / TPB, TPB>>>(b1);
    }
    k_score<<<(BATCH * 32 + TPB - 1) / TPB, TPB>>>(batch, relations, out);
}

// round 13
// speedup vs baseline: 1.0549x; 1.0549x over previous
#include <cuda_runtime.h>

#define N_NODES   50000
#define N_REL     10
#define R2        21
#define N_TRIPLES 500000
#define ETOT      (2 * N_TRIPLES + N_NODES)   // 1,050,000 augmented edges
#define BATCH     16384
#define KEYN      (N_NODES * R2)              // keys (src*21+p)
#define SCAN_CHUNK 4096
#define SCAN_NB   ((KEYN + SCAN_CHUNK - 1) / SCAN_CHUNK)   // 257
#define MAXFLAG   32768
#define NPW       4                           // nodes per warp in layer2

// Static scratch (no runtime allocation)
__device__ int   g_colsum[KEYN];
__device__ int   g_keycnt[KEYN];
__device__ int   g_keyoff[KEYN];
__device__ int   g_scanblk[512];
__device__ int   g_sorted[ETOT];
__device__ float g_h[N_NODES * 64];
__device__ float g_nodes[N_NODES * 64];
__device__ int   g_flag[N_NODES];
__device__ int   g_list[N_NODES];
__device__ int   g_cnt[1];
// Interleaved w1 for FFMA2 flush: [p][k2][lane] ulonglong2 where
//  .x = pack(w1[p][2*k2  ][2*lane], w1[p][2*k2  ][2*lane+1])
//  .y = pack(w1[p][2*k2+1][2*lane], w1[p][2*k2+1][2*lane+1])
__device__ ulonglong2 g_w1i[R2 * 32 * 32];

__device__ __forceinline__ unsigned long long pack2(float x, float y) {
    unsigned long long r;
    asm("mov.b64 %0, {%1, %2};" : "=l"(r) : "f"(x), "f"(y));
    return r;
}
__device__ __forceinline__ unsigned long long dup2(float x) {
    unsigned long long r;
    asm("mov.b64 %0, {%1, %1};" : "=l"(r) : "f"(x));
    return r;
}
__device__ __forceinline__ void unpack2(float& x, float& y, unsigned long long v) {
    asm("mov.b64 {%0, %1}, %2;" : "=f"(x), "=f"(y) : "l"(v));
}
__device__ __forceinline__ void ffma2(unsigned long long& acc,
                                      unsigned long long a, unsigned long long b) {
    asm("fma.rn.f32x2 %0, %1, %2, %0;" : "+l"(acc) : "l"(a), "l"(b));
}

__device__ __forceinline__ void decode_edge(int idx, const int* __restrict__ triples,
                                            int& src, int& p, int& o) {
    if (idx < N_TRIPLES) {
        src = triples[3 * idx + 0];
        p   = triples[3 * idx + 1];
        o   = triples[3 * idx + 2];
    } else if (idx < N_TRIPLES + N_NODES) {
        int i = idx - N_TRIPLES;
        src = i; p = 2 * N_REL; o = i;
    } else {
        int e = idx - N_TRIPLES - N_NODES;
        src = triples[3 * e + 2];
        p   = triples[3 * e + 1] + N_REL;
        o   = triples[3 * e + 0];
    }
}

// ---------------------------------------------------------------------------
// K0: zero counters/flags + build interleaved w1 (disjoint writes, safe)
// ---------------------------------------------------------------------------
__global__ void k_init(const float* __restrict__ w1) {
    int idx = blockIdx.x * blockDim.x + threadIdx.x;
    if (idx < KEYN) { g_colsum[idx] = 0; g_keycnt[idx] = 0; }
    if (idx < N_NODES) g_flag[idx] = 0;
    if (idx == 0) g_cnt[0] = 0;
    if (idx < R2 * 32 * 32) {
        int p = idx >> 10, rem = idx & 1023;
        int k2 = rem >> 5, lane = rem & 31;
        const float* base = w1 + p * 4096;
        float a0  = __ldg(base + (2 * k2)     * 64 + 2 * lane);
        float a1  = __ldg(base + (2 * k2)     * 64 + 2 * lane + 1);
        float b0  = __ldg(base + (2 * k2 + 1) * 64 + 2 * lane);
        float b1v = __ldg(base + (2 * k2 + 1) * 64 + 2 * lane + 1);
        ulonglong2 v;
        v.x = pack2(a0, a1);
        v.y = pack2(b0, b1v);
        g_w1i[idx] = v;
    }
}

// ---------------------------------------------------------------------------
// K1: histograms (+ batch-node flagging fused in; flags zeroed by k_init)
// ---------------------------------------------------------------------------
__global__ void k_hist(const int* __restrict__ triples, const int* __restrict__ batch) {
    int idx = blockIdx.x * blockDim.x + threadIdx.x;
    if (idx < BATCH) {
        g_flag[batch[3 * idx + 0]] = 1;
        g_flag[batch[3 * idx + 2]] = 1;
    }
    if (idx >= ETOT) return;
    int src, p, o;
    decode_edge(idx, triples, src, p, o);
    atomicAdd(&g_colsum[p * N_NODES + o], 1);
    atomicAdd(&g_keycnt[src * R2 + p], 1);
}

// ---------------------------------------------------------------------------
// 3-pass exclusive scan of g_keycnt -> g_keyoff
// ---------------------------------------------------------------------------
__global__ void k_scanA() {
    int b = blockIdx.x, tid = threadIdx.x;
    int base = b * SCAN_CHUNK + tid * 16;
    int s = 0;
    #pragma unroll
    for (int j = 0; j < 16; j++) {
        int idx = base + j;
        if (idx < KEYN) s += g_keycnt[idx];
    }
    __shared__ int sh[256];
    sh[tid] = s; __syncthreads();
    for (int off = 128; off; off >>= 1) {
        if (tid < off) sh[tid] += sh[tid + off];
        __syncthreads();
    }
    if (tid == 0) g_scanblk[b] = sh[0];
}

__global__ void k_scanB() {
    int tid = threadIdx.x;              // 512 threads, 1 block
    __shared__ int sh[512];
    int orig = (tid < SCAN_NB) ? g_scanblk[tid] : 0;
    sh[tid] = orig; __syncthreads();
    for (int off = 1; off < 512; off <<= 1) {
        int add = (tid >= off) ? sh[tid - off] : 0;
        __syncthreads();
        sh[tid] += add;
        __syncthreads();
    }
    if (tid < SCAN_NB) g_scanblk[tid] = sh[tid] - orig;   // exclusive
}

__global__ void k_scanC() {
    int b = blockIdx.x, tid = threadIdx.x;
    int base = b * SCAN_CHUNK + tid * 16;
    int v[16];
    #pragma unroll
    for (int j = 0; j < 16; j++) {
        int idx = base + j;
        v[j] = (idx < KEYN) ? g_keycnt[idx] : 0;
    }
    int tot = 0;
    #pragma unroll
    for (int j = 0; j < 16; j++) { int t = v[j]; v[j] = tot; tot += t; }
    __shared__ int sh[256];
    sh[tid] = tot; __syncthreads();
    int orig = tot;
    for (int off = 1; off < 256; off <<= 1) {
        int add = (tid >= off) ? sh[tid - off] : 0;
        __syncthreads();
        sh[tid] += add;
        __syncthreads();
    }
    int texcl = sh[tid] - orig + g_scanblk[b];
    #pragma unroll
    for (int j = 0; j < 16; j++) {
        int idx = base + j;
        if (idx < KEYN) g_keyoff[idx] = texcl + v[j];
    }
}

// ---------------------------------------------------------------------------
// Scatter: after this, g_keyoff[k] = exclusive END of key k
// ---------------------------------------------------------------------------
__global__ void k_scatter(const int* __restrict__ triples) {
    int idx = blockIdx.x * blockDim.x + threadIdx.x;
    if (idx >= ETOT) return;
    int src, p, o;
    decode_edge(idx, triples, src, p, o);
    int pos = atomicAdd(&g_keyoff[src * R2 + p], 1);
    g_sorted[pos] = (p << 16) | o;
}

// ---------------------------------------------------------------------------
// Layer 1: 16-thread group per node, register accumulation, no atomics.
// Inner loop chunked by 4: batch-issue independent loads (MLP 1 -> 4).
// ---------------------------------------------------------------------------
__global__ void k_layer1(const float* __restrict__ w0, const float* __restrict__ b0) {
    int t = blockIdx.x * blockDim.x + threadIdx.x;
    int u = t >> 4, lane = t & 15;
    if (u >= N_NODES) return;
    int s = (u == 0) ? 0 : g_keyoff[u * R2 - 1];
    int e = g_keyoff[u * R2 + R2 - 1];

    const float4* w0f4 = reinterpret_cast<const float4*>(w0);
    float4 acc = make_float4(0.f, 0.f, 0.f, 0.f);

    int i = s;
    for (; i + 4 <= e; i += 4) {
        int pk0 = g_sorted[i + 0];
        int pk1 = g_sorted[i + 1];
        int pk2 = g_sorted[i + 2];
        int pk3 = g_sorted[i + 3];
        int col0 = (pk0 >> 16) * N_NODES + (pk0 & 0xFFFF);
        int col1 = (pk1 >> 16) * N_NODES + (pk1 & 0xFFFF);
        int col2 = (pk2 >> 16) * N_NODES + (pk2 & 0xFFFF);
        int col3 = (pk3 >> 16) * N_NODES + (pk3 & 0xFFFF);
        int c0 = g_colsum[col0];
        int c1 = g_colsum[col1];
        int c2 = g_colsum[col2];
        int c3 = g_colsum[col3];
        float4 wa = __ldg(w0f4 + (size_t)col0 * 16 + lane);
        float4 wb = __ldg(w0f4 + (size_t)col1 * 16 + lane);
        float4 wc = __ldg(w0f4 + (size_t)col2 * 16 + lane);
        float4 wd = __ldg(w0f4 + (size_t)col3 * 16 + lane);
        float v0 = 1.0f / (float)c0;
        float v1 = 1.0f / (float)c1;
        float v2 = 1.0f / (float)c2;
        float v3 = 1.0f / (float)c3;
        acc.x = fmaf(v0, wa.x, acc.x); acc.y = fmaf(v0, wa.y, acc.y);
        acc.z = fmaf(v0, wa.z, acc.z); acc.w = fmaf(v0, wa.w, acc.w);
        acc.x = fmaf(v1, wb.x, acc.x); acc.y = fmaf(v1, wb.y, acc.y);
        acc.z = fmaf(v1, wb.z, acc.z); acc.w = fmaf(v1, wb.w, acc.w);
        acc.x = fmaf(v2, wc.x, acc.x); acc.y = fmaf(v2, wc.y, acc.y);
        acc.z = fmaf(v2, wc.z, acc.z); acc.w = fmaf(v2, wc.w, acc.w);
        acc.x = fmaf(v3, wd.x, acc.x); acc.y = fmaf(v3, wd.y, acc.y);
        acc.z = fmaf(v3, wd.z, acc.z); acc.w = fmaf(v3, wd.w, acc.w);
    }
    for (; i < e; i++) {
        int pk = g_sorted[i];
        int col = (pk >> 16) * N_NODES + (pk & 0xFFFF);
        float val = 1.0f / (float)g_colsum[col];
        float4 w = __ldg(w0f4 + (size_t)col * 16 + lane);
        acc.x = fmaf(val, w.x, acc.x);
        acc.y = fmaf(val, w.y, acc.y);
        acc.z = fmaf(val, w.z, acc.z);
        acc.w = fmaf(val, w.w, acc.w);
    }
    float4 bb = __ldg(reinterpret_cast<const float4*>(b0) + lane);
    float4 r = make_float4(bb.x + acc.x, bb.y + acc.y, bb.z + acc.z, bb.w + acc.w);
    *reinterpret_cast<float4*>(g_h + u * 64 + lane * 4) = r;
}

// ---------------------------------------------------------------------------
__global__ void k_compact() {
    int u = blockIdx.x * blockDim.x + threadIdx.x;
    if (u < N_NODES && g_flag[u]) {
        int i = atomicAdd(&g_cnt[0], 1);
        g_list[i] = u;
    }
}

// ---------------------------------------------------------------------------
// Layer 2: one warp per NPW=4 flagged nodes. Iterate p = 0..20; per p,
// segment bounds from consecutive g_keyoff entries; h-gather loop chunked
// by 4 for MLP; one W_p load feeds up to 4 accumulators via FFMA2.
// ---------------------------------------------------------------------------
__global__ void k_layer2(const float* __restrict__ b1) {
    int t = blockIdx.x * blockDim.x + threadIdx.x;
    int w = t >> 5, lane = t & 31;
    int wid = threadIdx.x >> 5;
    __shared__ __align__(16) float hs[8][NPW][64];

    int cnt = g_cnt[0];
    int base = w * NPW;
    if (base >= cnt) return;
    int nn = min(NPW, cnt - base);

    int u[NPW], prev[NPW];
    unsigned long long acc[NPW];
    #pragma unroll
    for (int n = 0; n < NPW; n++) {
        int un = (n < nn) ? g_list[base + n] : g_list[base];
        u[n] = un;
        prev[n] = (un == 0) ? 0 : g_keyoff[un * R2 - 1];
        acc[n] = 0ull;
    }

    for (int p = 0; p < R2; p++) {
        bool need[NPW];
        bool any = false;
        #pragma unroll
        for (int n = 0; n < NPW; n++) {
            int s = prev[n];
            int e = g_keyoff[u[n] * R2 + p];
            prev[n] = e;
            bool active = (n < nn) && (e > s);
            need[n] = active;
            if (active) {
                any = true;
                float2 hacc = make_float2(0.f, 0.f);
                int i = s;
                for (; i + 4 <= e; i += 4) {
                    int o0 = g_sorted[i + 0] & 0xFFFF;
                    int o1 = g_sorted[i + 1] & 0xFFFF;
                    int o2 = g_sorted[i + 2] & 0xFFFF;
                    int o3 = g_sorted[i + 3] & 0xFFFF;
                    int c0 = g_colsum[p * N_NODES + o0];
                    int c1 = g_colsum[p * N_NODES + o1];
                    int c2 = g_colsum[p * N_NODES + o2];
                    int c3 = g_colsum[p * N_NODES + o3];
                    float2 h0 = *reinterpret_cast<const float2*>(g_h + o0 * 64 + 2 * lane);
                    float2 h1 = *reinterpret_cast<const float2*>(g_h + o1 * 64 + 2 * lane);
                    float2 h2 = *reinterpret_cast<const float2*>(g_h + o2 * 64 + 2 * lane);
                    float2 h3 = *reinterpret_cast<const float2*>(g_h + o3 * 64 + 2 * lane);
                    float v0 = 1.0f / (float)c0;
                    float v1 = 1.0f / (float)c1;
                    float v2 = 1.0f / (float)c2;
                    float v3 = 1.0f / (float)c3;
                    hacc.x = fmaf(v0, h0.x, hacc.x); hacc.y = fmaf(v0, h0.y, hacc.y);
                    hacc.x = fmaf(v1, h1.x, hacc.x); hacc.y = fmaf(v1, h1.y, hacc.y);
                    hacc.x = fmaf(v2, h2.x, hacc.x); hacc.y = fmaf(v2, h2.y, hacc.y);
                    hacc.x = fmaf(v3, h3.x, hacc.x); hacc.y = fmaf(v3, h3.y, hacc.y);
                }
                for (; i < e; i++) {
                    int o = g_sorted[i] & 0xFFFF;
                    float val = 1.0f / (float)g_colsum[p * N_NODES + o];
                    float2 hv = *reinterpret_cast<const float2*>(g_h + o * 64 + 2 * lane);
                    hacc.x = fmaf(val, hv.x, hacc.x);
                    hacc.y = fmaf(val, hv.y, hacc.y);
                }
                *reinterpret_cast<float2*>(&hs[wid][n][2 * lane]) = hacc;
            }
        }
        if (!any) continue;
        __syncwarp();

        const ulonglong2* W = g_w1i + p * 1024 + lane;   // stride 32 per k2
        #pragma unroll 4
        for (int j = 0; j < 16; j++) {
            ulonglong2 w01 = __ldg(W + (2 * j) * 32);       // k = 4j, 4j+1
            ulonglong2 w23 = __ldg(W + (2 * j + 1) * 32);   // k = 4j+2, 4j+3
            #pragma unroll
            for (int n = 0; n < NPW; n++) {
                if (need[n]) {
                    float4 h4 = *reinterpret_cast<const float4*>(&hs[wid][n][4 * j]);
                    ffma2(acc[n], dup2(h4.x), w01.x);
                    ffma2(acc[n], dup2(h4.y), w01.y);
                    ffma2(acc[n], dup2(h4.z), w23.x);
                    ffma2(acc[n], dup2(h4.w), w23.y);
                }
            }
        }
        __syncwarp();
    }

    float2 bb = *reinterpret_cast<const float2*>(b1 + 2 * lane);
    #pragma unroll
    for (int n = 0; n < NPW; n++) {
        if (n < nn) {
            float c0, c1;
            unpack2(c0, c1, acc[n]);
            float2 r = make_float2(bb.x + c0, bb.y + c1);
            *reinterpret_cast<float2*>(g_nodes + u[n] * 64 + 2 * lane) = r;
        }
    }
}

// ---------------------------------------------------------------------------
__global__ void k_score(const int* __restrict__ batch, const float* __restrict__ rel,
                        float* __restrict__ out) {
    int t = blockIdx.x * blockDim.x + threadIdx.x;
    int b = t >> 5, lane = t & 31;
    if (b >= BATCH) return;
    int si = batch[3 * b + 0];
    int pi = batch[3 * b + 1];
    int oi = batch[3 * b + 2];
    const float* ns = g_nodes + si * 64;
    const float* no = g_nodes + oi * 64;
    const float* rr = rel + pi * 64;
    float a = ns[lane]      * rr[lane]      * no[lane]
            + ns[lane + 32] * rr[lane + 32] * no[lane + 32];
    #pragma unroll
    for (int off = 16; off; off >>= 1)
        a += __shfl_xor_sync(0xffffffffu, a, off);
    if (lane == 0) out[b] = a;
}

// ---------------------------------------------------------------------------
extern "C" void kernel_launch(void* const* d_in, const int* in_sizes, int n_in,
                              void* d_out, int out_size) {
    const int*   batch     = (const int*)  d_in[0];
    const int*   triples   = (const int*)  d_in[1];
    const float* w0        = (const float*)d_in[2];
    const float* b0        = (const float*)d_in[3];
    const float* w1        = (const float*)d_in[4];
    const float* b1        = (const float*)d_in[5];
    const float* relations = (const float*)d_in[6];
    float* out = (float*)d_out;

    const int TPB = 256;

    k_init<<<(KEYN + TPB - 1) / TPB, TPB>>>(w1);
    k_hist<<<(ETOT + TPB - 1) / TPB, TPB>>>(triples, batch);
    k_scanA<<<SCAN_NB, 256>>>();
    k_scanB<<<1, 512>>>();
    k_scanC<<<SCAN_NB, 256>>>();
    k_scatter<<<(ETOT + TPB - 1) / TPB, TPB>>>(triples);
    k_layer1<<<(N_NODES * 16 + TPB - 1) / TPB, TPB>>>(w0, b0);
    k_compact<<<(N_NODES + TPB - 1) / TPB, TPB>>>();
    {
        int warps = (MAXFLAG + NPW - 1) / NPW;           // 8192 warps
        k_layer2<<<(warps * 32 + TPB - 1) / TPB, TPB>>>(b1);
    }
    k_score<<<(BATCH * 32 + TPB - 1) / TPB, TPB>>>(batch, relations, out);
}